// round 8
// baseline (speedup 1.0000x reference)
#include <cuda_runtime.h>
#include <math.h>

#define FD 256

// -------- device scratch (zero-initialized at module load) --------
__device__ float g_dist[128 * 128];
__device__ float g_feat[128 * 128];
__device__ float g_md[128], g_fs[128], g_mf[128], g_mdist[128];
__device__ unsigned long long g_ckd[4][128], g_ckf[4][128];  // sharded col argmax
__device__ __align__(16) float g_geo[512];
__device__ float g_h1[256];
__device__ unsigned g_ctr1, g_ctr2, g_ctr3;

__device__ __forceinline__ unsigned f2o(float f) {
    unsigned u = __float_as_uint(f);
    return (u & 0x80000000u) ? ~u : (u | 0x80000000u);
}
__device__ __forceinline__ unsigned long long pk(float v, unsigned inv_idx) {
    return (((unsigned long long)f2o(v)) << 32) | (unsigned long long)inv_idx;
}
// release arrival / acquire spin (no L1 flush)
__device__ __forceinline__ void bar_arrive(unsigned* ctr) {
    asm volatile("red.release.gpu.add.u32 [%0], 1;" :: "l"(ctr) : "memory");
}
__device__ __forceinline__ void bar_spin(unsigned* ctr, unsigned target) {
    unsigned v;
    do {
        asm volatile("ld.acquire.gpu.u32 %0, [%1];" : "=r"(v) : "l"(ctr) : "memory");
    } while (v < target);
}
__device__ __forceinline__ void nbar(int id) {   // named barrier, 256 threads
    asm volatile("bar.sync %0, 256;" :: "r"(id) : "memory");
}

extern __shared__ float s_dyn[];   // block 0: W2 staging (128KB)

__global__ void __launch_bounds__(512)
k_all(const float* __restrict__ pts, const float* __restrict__ trans,
      const float* __restrict__ ref_f, const float* __restrict__ src_f,
      const float* __restrict__ W1, const float* __restrict__ b1,
      const float* __restrict__ gm1, const float* __restrict__ bt1,
      const float* __restrict__ W2, const float* __restrict__ b2,
      const float* __restrict__ gm2, const float* __restrict__ bt2,
      const float* __restrict__ W3, const float* __restrict__ b3,
      float* __restrict__ out) {
    __shared__ float spx[256], spy[256], spz[256], ssq[256];
    __shared__ __align__(16) float sref[FD];
    __shared__ float sdrow[128], sfrow[128];
    __shared__ float sred[24], smax[8];
    // prefetched per-block weights
    __shared__ __align__(16) float4 sW1[256];
    __shared__ float sb_fc1[2];
    // block-0 tail params
    __shared__ float sg1[256], sb1g[256];
    __shared__ float sg2[128], sbt2[128], sb2[128], sb3[2];
    __shared__ __align__(16) float4 sW3[64];
    // post-barrier work
    __shared__ float smd[256], sfs[256], smf[256], smdist[256];
    __shared__ __align__(16) unsigned long long sk1[256], sk2[256];
    __shared__ __align__(16) float sha[256];
    __shared__ float sh2[128];
    __shared__ __align__(16) float sh2a[128];

    const int t = threadIdx.x;
    const int i = blockIdx.x;
    const int w = t >> 5, lane = t & 31;
    const int slot = i & 3;

    // ============ prefetch (overlaps phase 1) ============
    if (t < 256) {
        sW1[t] = __ldg(&reinterpret_cast<const float4*>(W1)[i * 256 + t]);
    }
    if (t == 256) {
        sb_fc1[0] = __ldg(&b1[2 * i]);
        sb_fc1[1] = __ldg(&b1[2 * i + 1]);
    }
    if (i == 0) {
        if (t < 256) {
            sg1[t]  = __ldg(&gm1[t]);
            sb1g[t] = __ldg(&bt1[t]);
        } else if (t < 384) {
            int q = t - 256;
            sg2[q]  = __ldg(&gm2[q]);
            sbt2[q] = __ldg(&bt2[q]);
            sb2[q]  = __ldg(&b2[q]);
        } else if (t < 448) {
            sW3[t - 384] = __ldg(&reinterpret_cast<const float4*>(W3)[t - 384]);
        } else if (t < 450) {
            sb3[t - 448] = __ldg(&b3[t - 448]);
        }
        // stage W2 (128KB) into dynamic shared for the tail
        {
            float4* d4 = reinterpret_cast<float4*>(s_dyn);
            const float4* w4 = reinterpret_cast<const float4*>(W2);
#pragma unroll
            for (int q = 0; q < 16; q++)
                d4[t + 512 * q] = __ldg(&w4[t + 512 * q]);
        }
    }

    // =========== Phase 1 (warp-specialized): normalize+dist | feat ==========
    if (t < 256) {
        // ---- warps 0-7: point normalization + dist row ----
        float tr0 = __ldg(&trans[0]), tr1 = __ldg(&trans[1]), tr2  = __ldg(&trans[2]),  tr3  = __ldg(&trans[3]);
        float tr4 = __ldg(&trans[4]), tr5 = __ldg(&trans[5]), tr6  = __ldg(&trans[6]),  tr7  = __ldg(&trans[7]);
        float tr8 = __ldg(&trans[8]), tr9 = __ldg(&trans[9]), tr10 = __ldg(&trans[10]), tr11 = __ldg(&trans[11]);

        float px = pts[3 * t + 0];
        float py = pts[3 * t + 1];
        float pz = pts[3 * t + 2];
        if (t >= 128) {
            float x = tr0 * px + tr1 * py + tr2  * pz + tr3;
            float y = tr4 * px + tr5 * py + tr6  * pz + tr7;
            float z = tr8 * px + tr9 * py + tr10 * pz + tr11;
            px = x; py = y; pz = z;
        }
        float lx = px, ly = py, lz = pz;
#pragma unroll
        for (int o = 16; o > 0; o >>= 1) {
            lx += __shfl_xor_sync(0xffffffffu, lx, o);
            ly += __shfl_xor_sync(0xffffffffu, ly, o);
            lz += __shfl_xor_sync(0xffffffffu, lz, o);
        }
        if (lane == 0) { sred[w] = lx; sred[8 + w] = ly; sred[16 + w] = lz; }
        nbar(1);
        float cx = 0.f, cy = 0.f, cz = 0.f;
#pragma unroll
        for (int q = 0; q < 8; q++) { cx += sred[q]; cy += sred[8 + q]; cz += sred[16 + q]; }
        cx *= (1.0f / 256.0f); cy *= (1.0f / 256.0f); cz *= (1.0f / 256.0f);

        px -= cx; py -= cy; pz -= cz;
        float sq = px * px + py * py + pz * pz;
        float lm = sq;
#pragma unroll
        for (int o = 16; o > 0; o >>= 1)
            lm = fmaxf(lm, __shfl_xor_sync(0xffffffffu, lm, o));
        if (lane == 0) smax[w] = lm;
        nbar(1);
        float m2 = smax[0];
#pragma unroll
        for (int q = 1; q < 8; q++) m2 = fmaxf(m2, smax[q]);
        float inv = 1.0f / sqrtf(m2);
        spx[t] = px * inv; spy[t] = py * inv; spz[t] = pz * inv;
        ssq[t] = sq * inv * inv;
        nbar(1);

        if (t < 128) {
            float rx = spx[i], ry = spy[i], rz = spz[i];
            int sj = 128 + t;
            float d = ssq[i] + ssq[sj] - 2.0f * (rx * spx[sj] + ry * spy[sj] + rz * spz[sj]);
            d = fmaxf(d, 0.0f);
            float e = expf(-d);
            g_dist[i * 128 + t] = e;
            sdrow[t] = e;
            atomicMax(&g_ckd[slot][t], pk(e, 127u - (unsigned)i));
        }
    } else {
        // ---- warps 8-15: feature dots (16 src rows per warp) ----
        sref[t - 256] = __ldg(&ref_f[i * FD + (t - 256)]);
        nbar(2);
        const float4* sr4 = reinterpret_cast<const float4*>(sref);
        float4 r0 = sr4[lane];
        float4 r1 = sr4[lane + 32];
        int jb = (w - 8) * 16;
#pragma unroll 4
        for (int jj = 0; jj < 16; jj++) {
            int j = jb + jj;
            const float4* s4 = reinterpret_cast<const float4*>(src_f + (size_t)j * FD);
            float4 a0 = __ldg(&s4[lane]);
            float4 a1 = __ldg(&s4[lane + 32]);
            float acc = a0.x * r0.x + a0.y * r0.y + a0.z * r0.z + a0.w * r0.w
                      + a1.x * r1.x + a1.y * r1.y + a1.z * r1.z + a1.w * r1.w;
#pragma unroll
            for (int o = 16; o > 0; o >>= 1)
                acc += __shfl_xor_sync(0xffffffffu, acc, o);
            if (lane == 0) sfrow[j] = acc;
        }
    }
    __syncthreads();

    // feat matrix store + feat col atomics
    if (t < 128) {
        float fv = sfrow[t];
        g_feat[i * 128 + t] = fv;
        atomicMax(&g_ckf[slot][t], pk(fv, 127u - (unsigned)i));
    }
    // row argmaxes: warp 0 scans sdrow/sfrow
    if (w == 0) {
        unsigned long long kd = 0ull, kf = 0ull;
#pragma unroll
        for (int q = 0; q < 4; q++) {
            int idx = lane + 32 * q;
            unsigned long long cd = pk(sdrow[idx], 127u - (unsigned)idx);
            unsigned long long cf = pk(sfrow[idx], 127u - (unsigned)idx);
            if (cd > kd) kd = cd;
            if (cf > kf) kf = cf;
        }
#pragma unroll
        for (int o = 16; o > 0; o >>= 1) {
            unsigned long long od = __shfl_xor_sync(0xffffffffu, kd, o);
            unsigned long long of = __shfl_xor_sync(0xffffffffu, kf, o);
            if (od > kd) kd = od;
            if (of > kf) kf = of;
        }
        if (lane == 0) {
            int jd = 127 - (int)(kd & 0xFFFFFFFFull);
            int jf = 127 - (int)(kf & 0xFFFFFFFFull);
            g_md[i]    = sdrow[jd];
            g_fs[i]    = sfrow[jd];
            g_mf[i]    = sfrow[jf];
            g_mdist[i] = sdrow[jf];
        }
    }

    // ===================== grid barrier #1 =====================
    __syncthreads();
    if (t == 0) {
        bar_arrive(&g_ctr1);
        bar_spin(&g_ctr1, 128u);
    }
    __syncthreads();

    // ====== Phase 2: assemble + keys; each block ranks its 4 elements =======
    if (t < 128) {
        smd[t]    = __ldcg(&g_md[t]);
        sfs[t]    = __ldcg(&g_fs[t]);
        smf[t]    = __ldcg(&g_mf[t]);
        smdist[t] = __ldcg(&g_mdist[t]);
    } else if (t < 256) {
        int c = t - 128;
        unsigned long long kd = __ldcg(&g_ckd[0][c]);
        unsigned long long kf = __ldcg(&g_ckf[0][c]);
#pragma unroll
        for (int s = 1; s < 4; s++) {
            unsigned long long ud = __ldcg(&g_ckd[s][c]);
            unsigned long long uf = __ldcg(&g_ckf[s][c]);
            if (ud > kd) kd = ud;
            if (uf > kf) kf = uf;
        }
        int id = 127 - (int)(kd & 0xFFFFFFFFull);
        int jf = 127 - (int)(kf & 0xFFFFFFFFull);
        smd[t]    = __ldcg(&g_dist[id * 128 + c]);
        sfs[t]    = __ldcg(&g_feat[id * 128 + c]);
        smf[t]    = __ldcg(&g_feat[jf * 128 + c]);
        smdist[t] = __ldcg(&g_dist[jf * 128 + c]);
    }
    __syncthreads();

    if (t < 256) sk1[t] = pk(smd[t], 255u - (unsigned)t);
    else { int c = t - 256; sk2[c] = pk(smf[c], 255u - (unsigned)c); }
    __syncthreads();

    // one warp per owned element (4 per block)
    if (w < 4) {
        int e = 4 * i + w;
        const unsigned long long* keys = (e < 256) ? sk1 : sk2;
        int c = (e < 256) ? e : (e - 256);
        unsigned long long mykey = keys[c];
        int cnt = 0;
#pragma unroll
        for (int jj = 0; jj < 8; jj++)
            cnt += (keys[jj * 32 + lane] > mykey) ? 1 : 0;
#pragma unroll
        for (int o = 16; o > 0; o >>= 1)
            cnt += __shfl_xor_sync(0xffffffffu, cnt, o);
        if (lane == 0) {
            if (e < 256) g_geo[cnt]       = smd[c] * sfs[c];
            else         g_geo[256 + cnt] = smdist[c] * smf[c];
        }
    }
    __syncthreads();

    // ===================== grid barrier #2 (geo ready) =====================
    if (t == 0) {
        bar_arrive(&g_ctr2);
        bar_spin(&g_ctr2, 128u);
    }
    __syncthreads();

    // colkeys consumed by all blocks above -> reset own column across slots
    if (t == 32) {
#pragma unroll
        for (int s = 0; s < 4; s++) { g_ckd[s][i] = 0ull; g_ckf[s][i] = 0ull; }
    }

    // ================= Phase 3: fc1, 2 channels per block ===================
    if (w < 2) {
        const float4* geo4 = reinterpret_cast<const float4*>(g_geo);
        float acc = 0.0f;
#pragma unroll
        for (int q = 0; q < 4; q++) {
            float4 a = sW1[w * 128 + lane + 32 * q];
            float4 g = __ldcg(&geo4[lane + 32 * q]);
            acc += a.x * g.x + a.y * g.y + a.z * g.z + a.w * g.w;
        }
#pragma unroll
        for (int o = 16; o > 0; o >>= 1)
            acc += __shfl_xor_sync(0xffffffffu, acc, o);
        if (lane == 0) g_h1[2 * i + w] = acc + sb_fc1[w];
    }
    __syncthreads();

    // ===================== grid barrier #3 (h1 ready) =====================
    if (t == 0) bar_arrive(&g_ctr3);
    if (i != 0) return;
    if (t == 0) bar_spin(&g_ctr3, 128u);
    __syncthreads();

    // ============== Phase 4 (block 0): GN1+fc2+GN2+fc3 -> out ===============
    if (t < 256) {
        float x = __ldcg(&g_h1[t]);
        float s = x;
#pragma unroll
        for (int o = 16; o > 0; o >>= 1) s += __shfl_xor_sync(0xffffffffu, s, o);
        float mean = s * (1.0f / 32.0f);
        float ee = x - mean;
        float v = ee * ee;
#pragma unroll
        for (int o = 16; o > 0; o >>= 1) v += __shfl_xor_sync(0xffffffffu, v, o);
        v *= (1.0f / 32.0f);
        float xn = ee / sqrtf(v + 1e-5f) * sg1[t] + sb1g[t];
        sha[t] = fmaxf(xn, 0.0f);
    }
    __syncthreads();

    // fc2 from staged shared W2: 16 warps x 8 channels
    {
        const float4* ha4 = reinterpret_cast<const float4*>(sha);
        const float4* w24 = reinterpret_cast<const float4*>(s_dyn);
        float4 h0 = ha4[lane], h1v = ha4[lane + 32];
#pragma unroll 4
        for (int cc = 0; cc < 8; cc++) {
            int c = (w << 3) | cc;
            float4 a0 = w24[c * 64 + lane];
            float4 a1 = w24[c * 64 + lane + 32];
            float acc = a0.x * h0.x + a0.y * h0.y + a0.z * h0.z + a0.w * h0.w
                      + a1.x * h1v.x + a1.y * h1v.y + a1.z * h1v.z + a1.w * h1v.w;
#pragma unroll
            for (int o = 16; o > 0; o >>= 1)
                acc += __shfl_xor_sync(0xffffffffu, acc, o);
            if (lane == 0) sh2[c] = acc + sb2[c];
        }
    }
    __syncthreads();

    // GN2 (8 groups x 16 = half-warp per group) + ReLU
    if (t < 128) {
        float x = sh2[t];
        float s = x;
#pragma unroll
        for (int o = 8; o > 0; o >>= 1) s += __shfl_xor_sync(0xffffffffu, s, o);
        float mean = s * (1.0f / 16.0f);
        float ee = x - mean;
        float v = ee * ee;
#pragma unroll
        for (int o = 8; o > 0; o >>= 1) v += __shfl_xor_sync(0xffffffffu, v, o);
        v *= (1.0f / 16.0f);
        float xn = ee / sqrtf(v + 1e-5f) * sg2[t] + sbt2[t];
        sh2a[t] = fmaxf(xn, 0.0f);
    }
    __syncthreads();

    // fc3: 128 -> 2
    if (w < 2) {
        float4 a = sW3[w * 32 + lane];
        float4 g = reinterpret_cast<const float4*>(sh2a)[lane];
        float acc = a.x * g.x + a.y * g.y + a.z * g.z + a.w * g.w;
#pragma unroll
        for (int o = 16; o > 0; o >>= 1)
            acc += __shfl_xor_sync(0xffffffffu, acc, o);
        if (lane == 0) out[w] = acc + sb3[w];
    }

    // reset barrier counters for next graph replay
    if (t == 0) { g_ctr1 = 0u; g_ctr2 = 0u; g_ctr3 = 0u; }
}

extern "C" void kernel_launch(void* const* d_in, const int* in_sizes, int n_in,
                              void* d_out, int out_size) {
    const float* pts   = (const float*)d_in[0];
    const float* reff  = (const float*)d_in[1];
    const float* srcf  = (const float*)d_in[2];
    const float* trans = (const float*)d_in[3];
    const float* W1  = (const float*)d_in[4];
    const float* b1  = (const float*)d_in[5];
    const float* g1  = (const float*)d_in[6];
    const float* bt1 = (const float*)d_in[7];
    const float* W2  = (const float*)d_in[8];
    const float* b2  = (const float*)d_in[9];
    const float* g2  = (const float*)d_in[10];
    const float* bt2 = (const float*)d_in[11];
    const float* W3  = (const float*)d_in[12];
    const float* b3  = (const float*)d_in[13];

    const int DYN = 128 * 1024;   // W2 staging in block 0
    static bool attr_set = false;
    if (!attr_set) {
        cudaFuncSetAttribute(k_all, cudaFuncAttributeMaxDynamicSharedMemorySize, DYN);
        attr_set = true;
    }
    k_all<<<128, 512, DYN>>>(pts, trans, reff, srcf,
                             W1, b1, g1, bt1, W2, b2, g2, bt2, W3, b3,
                             (float*)d_out);
}

// round 9
// speedup vs baseline: 1.1355x; 1.1355x over previous
#include <cuda_runtime.h>
#include <math.h>

#define FD 256

// -------- device scratch (zero-initialized at module load) --------
__device__ float g_dist[128 * 128];
__device__ float g_feat[128 * 128];
__device__ float g_md[128], g_fs[128], g_mf[128], g_mdist[128];
__device__ unsigned long long g_ckd[4][128], g_ckf[4][128];  // sharded col argmax
__device__ __align__(16) float g_geo[512];
__device__ float g_h1[256];
__device__ unsigned g_ctr1, g_ctr2, g_ctr3;

__device__ __forceinline__ unsigned f2o(float f) {
    unsigned u = __float_as_uint(f);
    return (u & 0x80000000u) ? ~u : (u | 0x80000000u);
}
__device__ __forceinline__ unsigned long long pk(float v, unsigned inv_idx) {
    return (((unsigned long long)f2o(v)) << 32) | (unsigned long long)inv_idx;
}
// release arrival / acquire spin (no L1 flush)
__device__ __forceinline__ void bar_arrive(unsigned* ctr) {
    asm volatile("red.release.gpu.add.u32 [%0], 1;" :: "l"(ctr) : "memory");
}
__device__ __forceinline__ void bar_spin(unsigned* ctr, unsigned target) {
    unsigned v;
    do {
        asm volatile("ld.acquire.gpu.u32 %0, [%1];" : "=r"(v) : "l"(ctr) : "memory");
    } while (v < target);
}

__global__ void __launch_bounds__(512)
k_all(const float* __restrict__ pts, const float* __restrict__ trans,
      const float* __restrict__ ref_f, const float* __restrict__ src_f,
      const float* __restrict__ W1, const float* __restrict__ b1,
      const float* __restrict__ gm1, const float* __restrict__ bt1,
      const float* __restrict__ W2, const float* __restrict__ b2,
      const float* __restrict__ gm2, const float* __restrict__ bt2,
      const float* __restrict__ W3, const float* __restrict__ b3,
      float* __restrict__ out) {
    __shared__ float spx[256], spy[256], spz[256], ssq[256];
    __shared__ __align__(16) float sref[FD];
    __shared__ float sdrow[128], sfrow[128];
    __shared__ float sred[24], smax[8];
    // prefetched per-block weights
    __shared__ __align__(16) float4 sW1[256];   // W1 rows 2i, 2i+1
    __shared__ float sb_fc1[2];
    // block-0 tail params
    __shared__ float sg1[256], sb1g[256];
    __shared__ float sg2[128], sbt2[128], sb2[128], sb3[2];
    __shared__ __align__(16) float4 sW3[64];
    // post-barrier work
    __shared__ float smd[256], sfs[256], smf[256], smdist[256];
    __shared__ __align__(16) unsigned long long sk1[256], sk2[256];
    __shared__ __align__(16) float sha[256];
    __shared__ float sh2[128];
    __shared__ __align__(16) float sh2a[128];

    const int t = threadIdx.x;
    const int i = blockIdx.x;
    const int w = t >> 5, lane = t & 31;
    const int slot = i & 3;

    // ============ prefetch (overlaps phase 1) ============
    if (t < 256) {
        sW1[t]  = __ldg(&reinterpret_cast<const float4*>(W1)[i * 256 + t]);
        sref[t] = __ldg(&ref_f[i * FD + t]);
    }
    if (t == 256) {
        sb_fc1[0] = __ldg(&b1[2 * i]);
        sb_fc1[1] = __ldg(&b1[2 * i + 1]);
    }
    if (i == 0) {
        if (t < 256) {
            sg1[t]  = __ldg(&gm1[t]);
            sb1g[t] = __ldg(&bt1[t]);
        } else if (t < 384) {
            int q = t - 256;
            sg2[q]  = __ldg(&gm2[q]);
            sbt2[q] = __ldg(&bt2[q]);
            sb2[q]  = __ldg(&b2[q]);
        } else if (t < 448) {
            sW3[t - 384] = __ldg(&reinterpret_cast<const float4*>(W3)[t - 384]);
        } else if (t < 450) {
            sb3[t - 448] = __ldg(&b3[t - 448]);
        }
    }

    // ===================== Phase 1: normalize + my row ======================
    float tr0 = __ldg(&trans[0]), tr1 = __ldg(&trans[1]), tr2  = __ldg(&trans[2]),  tr3  = __ldg(&trans[3]);
    float tr4 = __ldg(&trans[4]), tr5 = __ldg(&trans[5]), tr6  = __ldg(&trans[6]),  tr7  = __ldg(&trans[7]);
    float tr8 = __ldg(&trans[8]), tr9 = __ldg(&trans[9]), tr10 = __ldg(&trans[10]), tr11 = __ldg(&trans[11]);

    float px = 0.f, py = 0.f, pz = 0.f;
    if (t < 256) {
        px = pts[3 * t + 0];
        py = pts[3 * t + 1];
        pz = pts[3 * t + 2];
        if (t >= 128) {
            float x = tr0 * px + tr1 * py + tr2  * pz + tr3;
            float y = tr4 * px + tr5 * py + tr6  * pz + tr7;
            float z = tr8 * px + tr9 * py + tr10 * pz + tr11;
            px = x; py = y; pz = z;
        }
    }
    float lx = px, ly = py, lz = pz;
#pragma unroll
    for (int o = 16; o > 0; o >>= 1) {
        lx += __shfl_xor_sync(0xffffffffu, lx, o);
        ly += __shfl_xor_sync(0xffffffffu, ly, o);
        lz += __shfl_xor_sync(0xffffffffu, lz, o);
    }
    if (w < 8 && lane == 0) { sred[w] = lx; sred[8 + w] = ly; sred[16 + w] = lz; }
    __syncthreads();
    float cx = 0.f, cy = 0.f, cz = 0.f;
#pragma unroll
    for (int q = 0; q < 8; q++) { cx += sred[q]; cy += sred[8 + q]; cz += sred[16 + q]; }
    cx *= (1.0f / 256.0f); cy *= (1.0f / 256.0f); cz *= (1.0f / 256.0f);

    float sq = 0.f;
    if (t < 256) {
        px -= cx; py -= cy; pz -= cz;
        sq = px * px + py * py + pz * pz;
    }
    float lm = sq;
#pragma unroll
    for (int o = 16; o > 0; o >>= 1)
        lm = fmaxf(lm, __shfl_xor_sync(0xffffffffu, lm, o));
    if (w < 8 && lane == 0) smax[w] = lm;
    __syncthreads();
    float m2 = smax[0];
#pragma unroll
    for (int q = 1; q < 8; q++) m2 = fmaxf(m2, smax[q]);
    float inv = 1.0f / sqrtf(m2);
    if (t < 256) {
        spx[t] = px * inv; spy[t] = py * inv; spz[t] = pz * inv;
        ssq[t] = sq * inv * inv;
    }
    __syncthreads();

    // dist entry (i, j=t) for t<128
    if (t < 128) {
        float rx = spx[i], ry = spy[i], rz = spz[i];
        int sj = 128 + t;
        float d = ssq[i] + ssq[sj] - 2.0f * (rx * spx[sj] + ry * spy[sj] + rz * spz[sj]);
        d = fmaxf(d, 0.0f);
        float e = expf(-d);
        g_dist[i * 128 + t] = e;
        sdrow[t] = e;
        atomicMax(&g_ckd[slot][t], pk(e, 127u - (unsigned)i));
    }

    // feat row: 16 warps x 8 src rows, coalesced
    {
        const float4* sr4 = reinterpret_cast<const float4*>(sref);
        float4 r0 = sr4[lane];
        float4 r1 = sr4[lane + 32];
        int jb = w * 8;
#pragma unroll
        for (int jj = 0; jj < 8; jj++) {
            int j = jb + jj;
            const float4* s4 = reinterpret_cast<const float4*>(src_f + (size_t)j * FD);
            float4 a0 = __ldg(&s4[lane]);
            float4 a1 = __ldg(&s4[lane + 32]);
            float acc = a0.x * r0.x + a0.y * r0.y + a0.z * r0.z + a0.w * r0.w
                      + a1.x * r1.x + a1.y * r1.y + a1.z * r1.z + a1.w * r1.w;
#pragma unroll
            for (int o = 16; o > 0; o >>= 1)
                acc += __shfl_xor_sync(0xffffffffu, acc, o);
            if (lane == 0) sfrow[j] = acc;
        }
    }
    __syncthreads();
    if (t < 128) {
        float fv = sfrow[t];
        g_feat[i * 128 + t] = fv;
        atomicMax(&g_ckf[slot][t], pk(fv, 127u - (unsigned)i));
    }
    // row argmaxes: warp 0 scans sdrow/sfrow
    if (w == 0) {
        unsigned long long kd = 0ull, kf = 0ull;
#pragma unroll
        for (int q = 0; q < 4; q++) {
            int idx = lane + 32 * q;
            unsigned long long cd = pk(sdrow[idx], 127u - (unsigned)idx);
            unsigned long long cf = pk(sfrow[idx], 127u - (unsigned)idx);
            if (cd > kd) kd = cd;
            if (cf > kf) kf = cf;
        }
#pragma unroll
        for (int o = 16; o > 0; o >>= 1) {
            unsigned long long od = __shfl_xor_sync(0xffffffffu, kd, o);
            unsigned long long of = __shfl_xor_sync(0xffffffffu, kf, o);
            if (od > kd) kd = od;
            if (of > kf) kf = of;
        }
        if (lane == 0) {
            int jd = 127 - (int)(kd & 0xFFFFFFFFull);
            int jf = 127 - (int)(kf & 0xFFFFFFFFull);
            g_md[i]    = sdrow[jd];
            g_fs[i]    = sfrow[jd];
            g_mf[i]    = sfrow[jf];
            g_mdist[i] = sdrow[jf];
        }
    }

    // ===================== grid barrier #1 =====================
    __syncthreads();
    if (t == 0) {
        bar_arrive(&g_ctr1);
        bar_spin(&g_ctr1, 128u);
    }
    __syncthreads();

    // ====== Phase 2: assemble + keys; each block ranks its 4 elements =======
    if (t < 128) {
        smd[t]    = __ldcg(&g_md[t]);
        sfs[t]    = __ldcg(&g_fs[t]);
        smf[t]    = __ldcg(&g_mf[t]);
        smdist[t] = __ldcg(&g_mdist[t]);
    } else if (t < 256) {
        int c = t - 128;
        unsigned long long kd = __ldcg(&g_ckd[0][c]);
        unsigned long long kf = __ldcg(&g_ckf[0][c]);
#pragma unroll
        for (int s = 1; s < 4; s++) {
            unsigned long long ud = __ldcg(&g_ckd[s][c]);
            unsigned long long uf = __ldcg(&g_ckf[s][c]);
            if (ud > kd) kd = ud;
            if (uf > kf) kf = uf;
        }
        int id = 127 - (int)(kd & 0xFFFFFFFFull);
        int jf = 127 - (int)(kf & 0xFFFFFFFFull);
        smd[t]    = __ldcg(&g_dist[id * 128 + c]);
        sfs[t]    = __ldcg(&g_feat[id * 128 + c]);
        smf[t]    = __ldcg(&g_feat[jf * 128 + c]);
        smdist[t] = __ldcg(&g_dist[jf * 128 + c]);
    }
    __syncthreads();

    if (t < 256) sk1[t] = pk(smd[t], 255u - (unsigned)t);
    else { int c = t - 256; sk2[c] = pk(smf[c], 255u - (unsigned)c); }
    __syncthreads();

    // one warp per owned element (4 per block across 128 blocks = 512 total)
    if (w < 4) {
        int e = 4 * i + w;
        const unsigned long long* keys = (e < 256) ? sk1 : sk2;
        int c = (e < 256) ? e : (e - 256);
        unsigned long long mykey = keys[c];
        int cnt = 0;
#pragma unroll
        for (int jj = 0; jj < 8; jj++)
            cnt += (keys[jj * 32 + lane] > mykey) ? 1 : 0;
#pragma unroll
        for (int o = 16; o > 0; o >>= 1)
            cnt += __shfl_xor_sync(0xffffffffu, cnt, o);
        if (lane == 0) {
            if (e < 256) g_geo[cnt]       = smd[c] * sfs[c];
            else         g_geo[256 + cnt] = smdist[c] * smf[c];
        }
    }
    __syncthreads();

    // ===================== grid barrier #2 (geo ready) =====================
    if (t == 0) {
        bar_arrive(&g_ctr2);
        bar_spin(&g_ctr2, 128u);
    }
    __syncthreads();

    // colkeys consumed by all blocks above -> reset own column across slots
    if (t == 32) {
#pragma unroll
        for (int s = 0; s < 4; s++) { g_ckd[s][i] = 0ull; g_ckf[s][i] = 0ull; }
    }

    // ================= Phase 3: fc1, 2 channels per block ===================
    if (w < 2) {
        const float4* geo4 = reinterpret_cast<const float4*>(g_geo);
        float acc = 0.0f;
#pragma unroll
        for (int q = 0; q < 4; q++) {
            float4 a = sW1[w * 128 + lane + 32 * q];
            float4 g = __ldcg(&geo4[lane + 32 * q]);
            acc += a.x * g.x + a.y * g.y + a.z * g.z + a.w * g.w;
        }
#pragma unroll
        for (int o = 16; o > 0; o >>= 1)
            acc += __shfl_xor_sync(0xffffffffu, acc, o);
        if (lane == 0) g_h1[2 * i + w] = acc + sb_fc1[w];
    }
    __syncthreads();

    // ===================== grid barrier #3 (h1 ready) =====================
    if (t == 0) bar_arrive(&g_ctr3);
    if (i != 0) return;                       // non-zero blocks done
    if (t == 0) bar_spin(&g_ctr3, 128u);
    __syncthreads();

    // ============== Phase 4 (block 0): GN1+fc2+GN2+fc3 -> out ===============
    if (t < 256) {
        float x = __ldcg(&g_h1[t]);
        float s = x;
#pragma unroll
        for (int o = 16; o > 0; o >>= 1) s += __shfl_xor_sync(0xffffffffu, s, o);
        float mean = s * (1.0f / 32.0f);
        float ee = x - mean;
        float v = ee * ee;
#pragma unroll
        for (int o = 16; o > 0; o >>= 1) v += __shfl_xor_sync(0xffffffffu, v, o);
        v *= (1.0f / 32.0f);
        float xn = ee / sqrtf(v + 1e-5f) * sg1[t] + sb1g[t];
        sha[t] = fmaxf(xn, 0.0f);
    }
    __syncthreads();

    // fc2: 16 warps x 8 channels, W2 from L2
    {
        const float4* ha4 = reinterpret_cast<const float4*>(sha);
        float4 h0 = ha4[lane], h1v = ha4[lane + 32];
#pragma unroll 4
        for (int cc = 0; cc < 8; cc++) {
            int c = (w << 3) | cc;
            const float4* row = reinterpret_cast<const float4*>(W2 + (size_t)c * 256);
            float4 a0 = __ldg(&row[lane]);
            float4 a1 = __ldg(&row[lane + 32]);
            float acc = a0.x * h0.x + a0.y * h0.y + a0.z * h0.z + a0.w * h0.w
                      + a1.x * h1v.x + a1.y * h1v.y + a1.z * h1v.z + a1.w * h1v.w;
#pragma unroll
            for (int o = 16; o > 0; o >>= 1)
                acc += __shfl_xor_sync(0xffffffffu, acc, o);
            if (lane == 0) sh2[c] = acc + sb2[c];
        }
    }
    __syncthreads();

    // GN2 (8 groups x 16 = half-warp per group) + ReLU
    if (t < 128) {
        float x = sh2[t];
        float s = x;
#pragma unroll
        for (int o = 8; o > 0; o >>= 1) s += __shfl_xor_sync(0xffffffffu, s, o);
        float mean = s * (1.0f / 16.0f);
        float ee = x - mean;
        float v = ee * ee;
#pragma unroll
        for (int o = 8; o > 0; o >>= 1) v += __shfl_xor_sync(0xffffffffu, v, o);
        v *= (1.0f / 16.0f);
        float xn = ee / sqrtf(v + 1e-5f) * sg2[t] + sbt2[t];
        sh2a[t] = fmaxf(xn, 0.0f);
    }
    __syncthreads();

    // fc3: 128 -> 2
    if (w < 2) {
        float4 a = sW3[w * 32 + lane];
        float4 g = reinterpret_cast<const float4*>(sh2a)[lane];
        float acc = a.x * g.x + a.y * g.y + a.z * g.z + a.w * g.w;
#pragma unroll
        for (int o = 16; o > 0; o >>= 1)
            acc += __shfl_xor_sync(0xffffffffu, acc, o);
        if (lane == 0) out[w] = acc + sb3[w];
    }

    // reset barrier counters for next graph replay
    if (t == 0) { g_ctr1 = 0u; g_ctr2 = 0u; g_ctr3 = 0u; }
}

extern "C" void kernel_launch(void* const* d_in, const int* in_sizes, int n_in,
                              void* d_out, int out_size) {
    const float* pts   = (const float*)d_in[0];
    const float* reff  = (const float*)d_in[1];
    const float* srcf  = (const float*)d_in[2];
    const float* trans = (const float*)d_in[3];
    const float* W1  = (const float*)d_in[4];
    const float* b1  = (const float*)d_in[5];
    const float* g1  = (const float*)d_in[6];
    const float* bt1 = (const float*)d_in[7];
    const float* W2  = (const float*)d_in[8];
    const float* b2  = (const float*)d_in[9];
    const float* g2  = (const float*)d_in[10];
    const float* bt2 = (const float*)d_in[11];
    const float* W3  = (const float*)d_in[12];
    const float* b3  = (const float*)d_in[13];

    k_all<<<128, 512>>>(pts, trans, reff, srcf,
                        W1, b1, g1, bt1, W2, b2, g2, bt2, W3, b3,
                        (float*)d_out);
}